// round 1
// baseline (speedup 1.0000x reference)
#include <cuda_runtime.h>
#include <math.h>
#include <float.h>

#define D_    1024
#define H_    16
#define HK_   8
#define HD_   64
#define FF_   3072
#define S_    1024
#define B_    4
#define TOK_  4096   // B*S
#define L_    4
#define WIN_  12

// ---------------- scratch (no allocations allowed) ----------------
__device__ float g_h   [TOK_ * D_];
__device__ float g_n   [TOK_ * D_];
__device__ float g_q   [TOK_ * H_  * HD_];
__device__ float g_k   [TOK_ * HK_ * HD_];
__device__ float g_v   [TOK_ * HK_ * HD_];
__device__ float g_att [TOK_ * H_  * HD_];
__device__ float g_gate[TOK_ * FF_];
__device__ float g_up  [TOK_ * FF_];

// ---------------- rmsnorm over 1024 cols, 1 block per row ----------------
__global__ void rmsnorm_kernel(const float* __restrict__ x,
                               const float* __restrict__ w,
                               float* __restrict__ out) {
    int row = blockIdx.x;
    const float* xr = x + (size_t)row * D_;
    int t = threadIdx.x;               // 256 threads, 4 floats each
    float4 v = *(const float4*)(xr + t * 4);
    float ss = v.x * v.x + v.y * v.y + v.z * v.z + v.w * v.w;
    #pragma unroll
    for (int o = 16; o; o >>= 1) ss += __shfl_xor_sync(0xffffffffu, ss, o);
    __shared__ float sh[8];
    if ((t & 31) == 0) sh[t >> 5] = ss;
    __syncthreads();
    float tot = 0.f;
    #pragma unroll
    for (int i = 0; i < 8; i++) tot += sh[i];
    float scale = rsqrtf(tot * (1.0f / D_) + 1e-6f);
    float4 wv = *(const float4*)(w + t * 4);
    float4 o4;
    o4.x = v.x * scale * wv.x;
    o4.y = v.y * scale * wv.y;
    o4.z = v.z * scale * wv.z;
    o4.w = v.w * scale * wv.w;
    *(float4*)(out + (size_t)row * D_ + t * 4) = o4;
}

// ---------------- generic fp32 GEMM: C[M,N] (+)= A[M,K] @ B[K,N] ----------------
// BM=BN=128, BK=16, 256 threads, 8x8 micro-tile
template <bool ACC>
__global__ void __launch_bounds__(256, 2)
gemm_kernel(const float* __restrict__ A, const float* __restrict__ B,
            float* __restrict__ C, int M, int N, int K) {
    __shared__ float As[16][132];   // transposed, padded
    __shared__ float Bs[16][128];

    int tid = threadIdx.x;
    int bx = blockIdx.x, by = blockIdx.y;
    int tx = tid & 15, ty = tid >> 4;

    const float* Ab = A + (size_t)(by * 128) * K;
    const float* Bb = B + bx * 128;

    int aRow = tid >> 2;            // 0..63
    int aCol = (tid & 3) << 2;      // 0,4,8,12
    int bRow = tid >> 5;            // 0..7
    int bCol = (tid & 31) << 2;     // 0..124

    float acc[8][8];
    #pragma unroll
    for (int i = 0; i < 8; i++)
        #pragma unroll
        for (int j = 0; j < 8; j++) acc[i][j] = 0.f;

    for (int k0 = 0; k0 < K; k0 += 16) {
        float4 a0 = *(const float4*)(Ab + (size_t)aRow * K + k0 + aCol);
        float4 a1 = *(const float4*)(Ab + (size_t)(aRow + 64) * K + k0 + aCol);
        float4 b0 = *(const float4*)(Bb + (size_t)(k0 + bRow) * N + bCol);
        float4 b1 = *(const float4*)(Bb + (size_t)(k0 + bRow + 8) * N + bCol);

        As[aCol + 0][aRow] = a0.x; As[aCol + 1][aRow] = a0.y;
        As[aCol + 2][aRow] = a0.z; As[aCol + 3][aRow] = a0.w;
        As[aCol + 0][aRow + 64] = a1.x; As[aCol + 1][aRow + 64] = a1.y;
        As[aCol + 2][aRow + 64] = a1.z; As[aCol + 3][aRow + 64] = a1.w;
        *(float4*)&Bs[bRow][bCol]     = b0;
        *(float4*)&Bs[bRow + 8][bCol] = b1;
        __syncthreads();

        #pragma unroll
        for (int kk = 0; kk < 16; kk++) {
            float ra[8], rb[8];
            *(float4*)(ra)     = *(const float4*)&As[kk][ty * 8];
            *(float4*)(ra + 4) = *(const float4*)&As[kk][ty * 8 + 4];
            *(float4*)(rb)     = *(const float4*)&Bs[kk][tx * 8];
            *(float4*)(rb + 4) = *(const float4*)&Bs[kk][tx * 8 + 4];
            #pragma unroll
            for (int i = 0; i < 8; i++)
                #pragma unroll
                for (int j = 0; j < 8; j++)
                    acc[i][j] = fmaf(ra[i], rb[j], acc[i][j]);
        }
        __syncthreads();
    }

    #pragma unroll
    for (int i = 0; i < 8; i++) {
        size_t row = (size_t)(by * 128 + ty * 8 + i);
        float* Cr = C + row * N + bx * 128 + tx * 8;
        #pragma unroll
        for (int j = 0; j < 8; j += 4) {
            float4 c4;
            if (ACC) {
                c4 = *(float4*)(Cr + j);
                c4.x += acc[i][j]; c4.y += acc[i][j + 1];
                c4.z += acc[i][j + 2]; c4.w += acc[i][j + 3];
            } else {
                c4.x = acc[i][j]; c4.y = acc[i][j + 1];
                c4.z = acc[i][j + 2]; c4.w = acc[i][j + 3];
            }
            *(float4*)(Cr + j) = c4;
        }
    }
}

// ---------------- per-head rmsnorm + RoPE (one warp per (token, head)) ----------------
__global__ void qknorm_rope_kernel(float* __restrict__ x,
                                   const float* __restrict__ w, int nh) {
    int warp = (blockIdx.x * blockDim.x + threadIdx.x) >> 5;
    int lane = threadIdx.x & 31;
    int token = warp / nh;
    int s = token & (S_ - 1);          // position within sequence
    float* p = x + (size_t)warp * HD_;
    float a = p[lane], b = p[lane + 32];
    float ss = a * a + b * b;
    #pragma unroll
    for (int o = 16; o; o >>= 1) ss += __shfl_xor_sync(0xffffffffu, ss, o);
    float scale = rsqrtf(ss * (1.0f / HD_) + 1e-6f);
    a *= scale * w[lane];
    b *= scale * w[lane + 32];
    // inv_freq = theta^(-lane/32); computed in double for accuracy
    float inv = (float)(1.0 / pow(1000000.0, (double)lane / 32.0));
    float ang = (float)s * inv;
    float c = cosf(ang), sn = sinf(ang);
    p[lane]      = a * c - b * sn;
    p[lane + 32] = b * c + a * sn;
}

// ---------------- flash attention: block = (b, h, 64 q rows), K-tile 32 ----------------
// win < 0 : full (pad-mask only).  win >= 0 : |q-k| <= win band.
__global__ void __launch_bounds__(256)
attn_kernel(const float* __restrict__ q, const float* __restrict__ k,
            const float* __restrict__ v, const int* __restrict__ amask,
            float* __restrict__ out, int win) {
    __shared__ float Qs[64][65];
    __shared__ float Ks[32][65];
    __shared__ float Vs[32][64];
    __shared__ float Ps[64][33];

    int b = blockIdx.z, h = blockIdx.y;
    int q0 = blockIdx.x * 64;
    int kh = h >> 1;                       // GQA: 2 q-heads per kv-head
    int tid = threadIdx.x;
    int tx = tid & 7;                      // 8 k-col groups (4 cols each)
    int tyg = tid >> 3;                    // 32 q-row groups (2 rows each)
    int r0 = tyg * 2, r1 = r0 + 1;
    int d0 = tx * 8;                       // 8 dims per thread in PV

    // load Q tile
    for (int i = tid; i < 64 * 16; i += 256) {
        int r = i >> 4, c4 = (i & 15) << 2;
        float4 f = *(const float4*)(q + ((size_t)(b * S_ + q0 + r) * (H_ * HD_)) + h * HD_ + c4);
        Qs[r][c4] = f.x; Qs[r][c4 + 1] = f.y; Qs[r][c4 + 2] = f.z; Qs[r][c4 + 3] = f.w;
    }

    float m0 = -1e30f, m1 = -1e30f, l0 = 0.f, l1 = 0.f;
    float o0[8], o1[8];
    #pragma unroll
    for (int j = 0; j < 8; j++) { o0[j] = 0.f; o1[j] = 0.f; }

    int kt_lo = 0, kt_hi = (S_ / 32) - 1;
    if (win >= 0) {
        int lo = q0 - win; if (lo < 0) lo = 0;
        int hi = q0 + 63 + win; if (hi > S_ - 1) hi = S_ - 1;
        kt_lo = lo >> 5; kt_hi = hi >> 5;
    }
    const float scale = 0.125f;            // 1/sqrt(64)

    __syncthreads();
    for (int kt = kt_lo; kt <= kt_hi; kt++) {
        int kbase = b * S_ + kt * 32;
        for (int i = tid; i < 32 * 16; i += 256) {
            int r = i >> 4, c4 = (i & 15) << 2;
            size_t off = (size_t)(kbase + r) * (HK_ * HD_) + kh * HD_ + c4;
            float4 fk = *(const float4*)(k + off);
            float4 fv = *(const float4*)(v + off);
            Ks[r][c4] = fk.x; Ks[r][c4 + 1] = fk.y; Ks[r][c4 + 2] = fk.z; Ks[r][c4 + 3] = fk.w;
            *(float4*)&Vs[r][c4] = fv;
        }
        __syncthreads();

        float s0[4], s1[4];
        #pragma unroll
        for (int j = 0; j < 4; j++) { s0[j] = 0.f; s1[j] = 0.f; }
        #pragma unroll 8
        for (int d = 0; d < 64; d++) {
            float qa = Qs[r0][d], qb = Qs[r1][d];
            #pragma unroll
            for (int j = 0; j < 4; j++) {
                float kv = Ks[tx * 4 + j][d];
                s0[j] = fmaf(qa, kv, s0[j]);
                s1[j] = fmaf(qb, kv, s1[j]);
            }
        }
        // scale + mask
        #pragma unroll
        for (int j = 0; j < 4; j++) {
            int kpos = kt * 32 + tx * 4 + j;
            bool ok = (amask[b * S_ + kpos] != 0);
            float sa = s0[j] * scale, sb = s1[j] * scale;
            if (win >= 0) {
                int qa_ = q0 + r0, qb_ = q0 + r1;
                if (abs(qa_ - kpos) > win) sa = -1e30f;
                if (abs(qb_ - kpos) > win) sb = -1e30f;
            }
            if (!ok) { sa = -1e30f; sb = -1e30f; }
            s0[j] = sa; s1[j] = sb;
        }
        // online softmax, row 0
        {
            float tm = fmaxf(fmaxf(s0[0], s0[1]), fmaxf(s0[2], s0[3]));
            #pragma unroll
            for (int o = 4; o; o >>= 1) tm = fmaxf(tm, __shfl_xor_sync(0xffffffffu, tm, o));
            float nm = fmaxf(m0, tm);
            float alpha = expf(m0 - nm);
            float ps = 0.f;
            #pragma unroll
            for (int j = 0; j < 4; j++) {
                float p = expf(s0[j] - nm);
                Ps[r0][tx * 4 + j] = p;
                ps += p;
            }
            #pragma unroll
            for (int o = 4; o; o >>= 1) ps += __shfl_xor_sync(0xffffffffu, ps, o);
            l0 = l0 * alpha + ps; m0 = nm;
            #pragma unroll
            for (int j = 0; j < 8; j++) o0[j] *= alpha;
        }
        // row 1
        {
            float tm = fmaxf(fmaxf(s1[0], s1[1]), fmaxf(s1[2], s1[3]));
            #pragma unroll
            for (int o = 4; o; o >>= 1) tm = fmaxf(tm, __shfl_xor_sync(0xffffffffu, tm, o));
            float nm = fmaxf(m1, tm);
            float alpha = expf(m1 - nm);
            float ps = 0.f;
            #pragma unroll
            for (int j = 0; j < 4; j++) {
                float p = expf(s1[j] - nm);
                Ps[r1][tx * 4 + j] = p;
                ps += p;
            }
            #pragma unroll
            for (int o = 4; o; o >>= 1) ps += __shfl_xor_sync(0xffffffffu, ps, o);
            l1 = l1 * alpha + ps; m1 = nm;
            #pragma unroll
            for (int j = 0; j < 8; j++) o1[j] *= alpha;
        }
        __syncthreads();
        // O += P @ V
        #pragma unroll 4
        for (int kk = 0; kk < 32; kk++) {
            float p0 = Ps[r0][kk], p1 = Ps[r1][kk];
            #pragma unroll
            for (int j = 0; j < 8; j++) {
                float vv = Vs[kk][d0 + j];
                o0[j] = fmaf(p0, vv, o0[j]);
                o1[j] = fmaf(p1, vv, o1[j]);
            }
        }
        __syncthreads();
    }

    float il0 = 1.0f / l0, il1 = 1.0f / l1;
    size_t base0 = (size_t)(b * S_ + q0 + r0) * (H_ * HD_) + h * HD_ + d0;
    size_t base1 = (size_t)(b * S_ + q0 + r1) * (H_ * HD_) + h * HD_ + d0;
    #pragma unroll
    for (int j = 0; j < 8; j++) {
        out[base0 + j] = o0[j] * il0;
        out[base1 + j] = o1[j] * il1;
    }
}

// ---------------- SwiGLU elementwise: gate = silu(gate) * up ----------------
__global__ void silu_mul_kernel(float* __restrict__ gate,
                                const float* __restrict__ up, int n) {
    int i = blockIdx.x * blockDim.x + threadIdx.x;
    if (i < n) {
        float g = gate[i];
        float s = g / (1.0f + expf(-g));
        gate[i] = s * up[i];
    }
}

// ---------------- host orchestration ----------------
extern "C" void kernel_launch(void* const* d_in, const int* in_sizes, int n_in,
                              void* d_out, int out_size) {
    const float* x      = (const float*)d_in[0];
    const float* wq     = (const float*)d_in[1];
    const float* wk     = (const float*)d_in[2];
    const float* wv     = (const float*)d_in[3];
    const float* wo     = (const float*)d_in[4];
    const float* qnw    = (const float*)d_in[5];
    const float* knw    = (const float*)d_in[6];
    const float* ln1    = (const float*)d_in[7];
    const float* ln2    = (const float*)d_in[8];
    const float* wg     = (const float*)d_in[9];
    const float* wu     = (const float*)d_in[10];
    const float* wd     = (const float*)d_in[11];
    const float* normw  = (const float*)d_in[12];
    const int*   amask  = (const int*)d_in[13];

    float *h, *n, *q, *k, *v, *att, *gate, *up;
    cudaGetSymbolAddress((void**)&h,    g_h);
    cudaGetSymbolAddress((void**)&n,    g_n);
    cudaGetSymbolAddress((void**)&q,    g_q);
    cudaGetSymbolAddress((void**)&k,    g_k);
    cudaGetSymbolAddress((void**)&v,    g_v);
    cudaGetSymbolAddress((void**)&att,  g_att);
    cudaGetSymbolAddress((void**)&gate, g_gate);
    cudaGetSymbolAddress((void**)&up,   g_up);

    cudaMemcpyAsync(h, x, (size_t)TOK_ * D_ * sizeof(float),
                    cudaMemcpyDeviceToDevice, 0);

    dim3 g1024(D_ / 128, TOK_ / 128);        // N=1024
    dim3 g512 ((HK_ * HD_) / 128, TOK_ / 128);
    dim3 g3072(FF_ / 128, TOK_ / 128);

    for (int l = 0; l < L_; l++) {
        const float* wq_l = wq + (size_t)l * D_ * H_ * HD_;
        const float* wk_l = wk + (size_t)l * D_ * HK_ * HD_;
        const float* wv_l = wv + (size_t)l * D_ * HK_ * HD_;
        const float* wo_l = wo + (size_t)l * H_ * HD_ * D_;
        const float* wg_l = wg + (size_t)l * D_ * FF_;
        const float* wu_l = wu + (size_t)l * D_ * FF_;
        const float* wd_l = wd + (size_t)l * FF_ * D_;

        rmsnorm_kernel<<<TOK_, 256>>>(h, ln1 + l * D_, n);

        gemm_kernel<false><<<g1024, 256>>>(n, wq_l, q,  TOK_, H_  * HD_, D_);
        gemm_kernel<false><<<g512,  256>>>(n, wk_l, k,  TOK_, HK_ * HD_, D_);
        gemm_kernel<false><<<g512,  256>>>(n, wv_l, v,  TOK_, HK_ * HD_, D_);

        qknorm_rope_kernel<<<(TOK_ * H_)  / 4, 128>>>(q, qnw + l * HD_, H_);
        qknorm_rope_kernel<<<(TOK_ * HK_) / 4, 128>>>(k, knw + l * HD_, HK_);

        attn_kernel<<<dim3(S_ / 64, H_, B_), 256>>>(
            q, k, v, amask, att, (l & 1) ? WIN_ : -1);

        gemm_kernel<true><<<g1024, 256>>>(att, wo_l, h, TOK_, D_, H_ * HD_);

        rmsnorm_kernel<<<TOK_, 256>>>(h, ln2 + l * D_, n);

        gemm_kernel<false><<<g3072, 256>>>(n, wg_l, gate, TOK_, FF_, D_);
        gemm_kernel<false><<<g3072, 256>>>(n, wu_l, up,   TOK_, FF_, D_);

        int nel = TOK_ * FF_;
        silu_mul_kernel<<<(nel + 255) / 256, 256>>>(gate, up, nel);

        gemm_kernel<true><<<g1024, 256>>>(gate, wd_l, h, TOK_, D_, FF_);
    }

    rmsnorm_kernel<<<TOK_, 256>>>(h, normw, (float*)d_out);
}

// round 2
// speedup vs baseline: 1.6452x; 1.6452x over previous
#include <cuda_runtime.h>
#include <math.h>
#include <float.h>

#define D_    1024
#define H_    16
#define HK_   8
#define HD_   64
#define FF_   3072
#define S_    1024
#define B_    4
#define TOK_  4096   // B*S
#define L_    4
#define WIN_  12

// ---------------- scratch (no allocations allowed) ----------------
__device__ float g_h   [TOK_ * D_];
__device__ float g_n   [TOK_ * D_];
__device__ float g_q   [TOK_ * H_  * HD_];
__device__ float g_k   [TOK_ * HK_ * HD_];
__device__ float g_v   [TOK_ * HK_ * HD_];
__device__ float g_att [TOK_ * H_  * HD_];
__device__ float g_gate[TOK_ * FF_];
__device__ float g_up  [TOK_ * FF_];

// ---------------- rmsnorm over 1024 cols, 1 block per row ----------------
__global__ void rmsnorm_kernel(const float* __restrict__ x,
                               const float* __restrict__ w,
                               float* __restrict__ out) {
    int row = blockIdx.x;
    const float* xr = x + (size_t)row * D_;
    int t = threadIdx.x;               // 256 threads, 4 floats each
    float4 v = *(const float4*)(xr + t * 4);
    float ss = v.x * v.x + v.y * v.y + v.z * v.z + v.w * v.w;
    #pragma unroll
    for (int o = 16; o; o >>= 1) ss += __shfl_xor_sync(0xffffffffu, ss, o);
    __shared__ float sh[8];
    if ((t & 31) == 0) sh[t >> 5] = ss;
    __syncthreads();
    float tot = 0.f;
    #pragma unroll
    for (int i = 0; i < 8; i++) tot += sh[i];
    float scale = rsqrtf(tot * (1.0f / D_) + 1e-6f);
    float4 wv = *(const float4*)(w + t * 4);
    float4 o4;
    o4.x = v.x * scale * wv.x;
    o4.y = v.y * scale * wv.y;
    o4.z = v.z * scale * wv.z;
    o4.w = v.w * scale * wv.w;
    *(float4*)(out + (size_t)row * D_ + t * 4) = o4;
}

// ---------------- tf32 → bits helper (round-to-nearest) ----------------
__device__ __forceinline__ unsigned f2tf(float x) {
    unsigned r;
    asm("cvt.rna.tf32.f32 %0, %1;" : "=r"(r) : "f"(x));
    return r;
}

// ---------------- TF32 tensor-core GEMM: C[M,N] (+)= A[M,K] @ B[K,N] ----------------
// BM=BN=128, BK=16, 256 threads (8 warps, 2x4). Warp tile 64x32 via 4x4 m16n8k8.
// Smem k-major with row stride 136 (bank-conflict-free fragment loads).
template <bool ACC>
__global__ void __launch_bounds__(256, 2)
gemm_tf32(const float* __restrict__ A, const float* __restrict__ B,
          float* __restrict__ C, int M, int N, int K) {
    __shared__ unsigned As[2][16][136];
    __shared__ unsigned Bs[2][16][136];

    int tid = threadIdx.x;
    int lane = tid & 31, wid = tid >> 5;
    int wr = wid >> 2;          // 0..1  (64-row slab)
    int wc = wid & 3;           // 0..3  (32-col slab)
    int tg = lane & 3;          // thread-in-group (k index)
    int grp = lane >> 2;        // group (m/n index)
    int bx = blockIdx.x, by = blockIdx.y;

    const float* Ag = A + (size_t)(by * 128) * K;
    const float* Bg = B + bx * 128;

    // global-load index plan: 2 float4 per thread for each of A and B
    int af0 = tid * 2, af1 = tid * 2 + 1;
    int ar0 = af0 >> 2, ac0 = (af0 & 3) << 2;
    int ar1 = af1 >> 2, ac1 = (af1 & 3) << 2;
    int br0 = af0 >> 5, bc0 = (af0 & 31) << 2;
    int br1 = af1 >> 5, bc1 = (af1 & 31) << 2;

    float acc[4][4][4];
    #pragma unroll
    for (int i = 0; i < 4; i++)
        #pragma unroll
        for (int j = 0; j < 4; j++)
            #pragma unroll
            for (int c = 0; c < 4; c++) acc[i][j][c] = 0.f;

    float4 a0g, a1g, b0g, b1g;

    // prologue: load tile 0
    a0g = *(const float4*)(Ag + (size_t)ar0 * K + ac0);
    a1g = *(const float4*)(Ag + (size_t)ar1 * K + ac1);
    b0g = *(const float4*)(Bg + (size_t)br0 * N + bc0);
    b1g = *(const float4*)(Bg + (size_t)br1 * N + bc1);
    {
        As[0][ac0 + 0][ar0] = f2tf(a0g.x); As[0][ac0 + 1][ar0] = f2tf(a0g.y);
        As[0][ac0 + 2][ar0] = f2tf(a0g.z); As[0][ac0 + 3][ar0] = f2tf(a0g.w);
        As[0][ac1 + 0][ar1] = f2tf(a1g.x); As[0][ac1 + 1][ar1] = f2tf(a1g.y);
        As[0][ac1 + 2][ar1] = f2tf(a1g.z); As[0][ac1 + 3][ar1] = f2tf(a1g.w);
        uint4 u0 = make_uint4(f2tf(b0g.x), f2tf(b0g.y), f2tf(b0g.z), f2tf(b0g.w));
        uint4 u1 = make_uint4(f2tf(b1g.x), f2tf(b1g.y), f2tf(b1g.z), f2tf(b1g.w));
        *(uint4*)&Bs[0][br0][bc0] = u0;
        *(uint4*)&Bs[0][br1][bc1] = u1;
    }
    __syncthreads();

    int nIter = K >> 4;
    int cur = 0;
    for (int it = 0; it < nIter; it++) {
        int k0n = (it + 1) << 4;
        bool hasNext = (it + 1) < nIter;
        if (hasNext) {
            a0g = *(const float4*)(Ag + (size_t)ar0 * K + k0n + ac0);
            a1g = *(const float4*)(Ag + (size_t)ar1 * K + k0n + ac1);
            b0g = *(const float4*)(Bg + (size_t)(k0n + br0) * N + bc0);
            b1g = *(const float4*)(Bg + (size_t)(k0n + br1) * N + bc1);
        }

        #pragma unroll
        for (int kk = 0; kk < 16; kk += 8) {
            unsigned afr[4][4], bfr[4][2];
            #pragma unroll
            for (int mt = 0; mt < 4; mt++) {
                int m = wr * 64 + mt * 16 + grp;
                afr[mt][0] = As[cur][kk + tg][m];
                afr[mt][1] = As[cur][kk + tg][m + 8];
                afr[mt][2] = As[cur][kk + tg + 4][m];
                afr[mt][3] = As[cur][kk + tg + 4][m + 8];
            }
            #pragma unroll
            for (int nt = 0; nt < 4; nt++) {
                int n = wc * 32 + nt * 8 + grp;
                bfr[nt][0] = Bs[cur][kk + tg][n];
                bfr[nt][1] = Bs[cur][kk + tg + 4][n];
            }
            #pragma unroll
            for (int mt = 0; mt < 4; mt++)
                #pragma unroll
                for (int nt = 0; nt < 4; nt++) {
                    asm volatile(
                        "mma.sync.aligned.m16n8k8.row.col.f32.tf32.tf32.f32 "
                        "{%0,%1,%2,%3}, {%4,%5,%6,%7}, {%8,%9}, {%0,%1,%2,%3};"
                        : "+f"(acc[mt][nt][0]), "+f"(acc[mt][nt][1]),
                          "+f"(acc[mt][nt][2]), "+f"(acc[mt][nt][3])
                        : "r"(afr[mt][0]), "r"(afr[mt][1]),
                          "r"(afr[mt][2]), "r"(afr[mt][3]),
                          "r"(bfr[nt][0]), "r"(bfr[nt][1]));
                }
        }

        if (hasNext) {
            int nxt = cur ^ 1;
            As[nxt][ac0 + 0][ar0] = f2tf(a0g.x); As[nxt][ac0 + 1][ar0] = f2tf(a0g.y);
            As[nxt][ac0 + 2][ar0] = f2tf(a0g.z); As[nxt][ac0 + 3][ar0] = f2tf(a0g.w);
            As[nxt][ac1 + 0][ar1] = f2tf(a1g.x); As[nxt][ac1 + 1][ar1] = f2tf(a1g.y);
            As[nxt][ac1 + 2][ar1] = f2tf(a1g.z); As[nxt][ac1 + 3][ar1] = f2tf(a1g.w);
            uint4 u0 = make_uint4(f2tf(b0g.x), f2tf(b0g.y), f2tf(b0g.z), f2tf(b0g.w));
            uint4 u1 = make_uint4(f2tf(b1g.x), f2tf(b1g.y), f2tf(b1g.z), f2tf(b1g.w));
            *(uint4*)&Bs[nxt][br0][bc0] = u0;
            *(uint4*)&Bs[nxt][br1][bc1] = u1;
            __syncthreads();
            cur = nxt;
        }
    }

    // epilogue
    #pragma unroll
    for (int mt = 0; mt < 4; mt++) {
        int row0 = by * 128 + wr * 64 + mt * 16 + grp;
        #pragma unroll
        for (int nt = 0; nt < 4; nt++) {
            int col = bx * 128 + wc * 32 + nt * 8 + tg * 2;
            float* p0 = C + (size_t)row0 * N + col;
            float* p1 = C + (size_t)(row0 + 8) * N + col;
            if (ACC) {
                float2 c0 = *(float2*)p0, c1 = *(float2*)p1;
                c0.x += acc[mt][nt][0]; c0.y += acc[mt][nt][1];
                c1.x += acc[mt][nt][2]; c1.y += acc[mt][nt][3];
                *(float2*)p0 = c0; *(float2*)p1 = c1;
            } else {
                *(float2*)p0 = make_float2(acc[mt][nt][0], acc[mt][nt][1]);
                *(float2*)p1 = make_float2(acc[mt][nt][2], acc[mt][nt][3]);
            }
        }
    }
}

// ---------------- per-head rmsnorm + RoPE (one warp per (token, head)) ----------------
__global__ void qknorm_rope_kernel(float* __restrict__ x,
                                   const float* __restrict__ w, int nh) {
    int warp = (blockIdx.x * blockDim.x + threadIdx.x) >> 5;
    int lane = threadIdx.x & 31;
    int token = warp / nh;
    int s = token & (S_ - 1);          // position within sequence
    float* p = x + (size_t)warp * HD_;
    float a = p[lane], b = p[lane + 32];
    float ss = a * a + b * b;
    #pragma unroll
    for (int o = 16; o; o >>= 1) ss += __shfl_xor_sync(0xffffffffu, ss, o);
    float scale = rsqrtf(ss * (1.0f / HD_) + 1e-6f);
    a *= scale * w[lane];
    b *= scale * w[lane + 32];
    float inv = (float)(1.0 / pow(1000000.0, (double)lane / 32.0));
    float ang = (float)s * inv;
    float c = cosf(ang), sn = sinf(ang);
    p[lane]      = a * c - b * sn;
    p[lane + 32] = b * c + a * sn;
}

// ---------------- flash attention: block = (b, h, 64 q rows), K-tile 32 ----------------
__global__ void __launch_bounds__(256)
attn_kernel(const float* __restrict__ q, const float* __restrict__ k,
            const float* __restrict__ v, const int* __restrict__ amask,
            float* __restrict__ out, int win) {
    __shared__ float Qs[64][65];
    __shared__ float Ks[32][65];
    __shared__ float Vs[32][64];
    __shared__ float Ps[64][33];

    int b = blockIdx.z, h = blockIdx.y;
    int q0 = blockIdx.x * 64;
    int kh = h >> 1;                       // GQA: 2 q-heads per kv-head
    int tid = threadIdx.x;
    int tx = tid & 7;
    int tyg = tid >> 3;
    int r0 = tyg * 2, r1 = r0 + 1;
    int d0 = tx * 8;

    for (int i = tid; i < 64 * 16; i += 256) {
        int r = i >> 4, c4 = (i & 15) << 2;
        float4 f = *(const float4*)(q + ((size_t)(b * S_ + q0 + r) * (H_ * HD_)) + h * HD_ + c4);
        Qs[r][c4] = f.x; Qs[r][c4 + 1] = f.y; Qs[r][c4 + 2] = f.z; Qs[r][c4 + 3] = f.w;
    }

    float m0 = -1e30f, m1 = -1e30f, l0 = 0.f, l1 = 0.f;
    float o0[8], o1[8];
    #pragma unroll
    for (int j = 0; j < 8; j++) { o0[j] = 0.f; o1[j] = 0.f; }

    int kt_lo = 0, kt_hi = (S_ / 32) - 1;
    if (win >= 0) {
        int lo = q0 - win; if (lo < 0) lo = 0;
        int hi = q0 + 63 + win; if (hi > S_ - 1) hi = S_ - 1;
        kt_lo = lo >> 5; kt_hi = hi >> 5;
    }
    const float scale = 0.125f;

    __syncthreads();
    for (int kt = kt_lo; kt <= kt_hi; kt++) {
        int kbase = b * S_ + kt * 32;
        for (int i = tid; i < 32 * 16; i += 256) {
            int r = i >> 4, c4 = (i & 15) << 2;
            size_t off = (size_t)(kbase + r) * (HK_ * HD_) + kh * HD_ + c4;
            float4 fk = *(const float4*)(k + off);
            float4 fv = *(const float4*)(v + off);
            Ks[r][c4] = fk.x; Ks[r][c4 + 1] = fk.y; Ks[r][c4 + 2] = fk.z; Ks[r][c4 + 3] = fk.w;
            *(float4*)&Vs[r][c4] = fv;
        }
        __syncthreads();

        float s0[4], s1[4];
        #pragma unroll
        for (int j = 0; j < 4; j++) { s0[j] = 0.f; s1[j] = 0.f; }
        #pragma unroll 8
        for (int d = 0; d < 64; d++) {
            float qa = Qs[r0][d], qb = Qs[r1][d];
            #pragma unroll
            for (int j = 0; j < 4; j++) {
                float kv = Ks[tx * 4 + j][d];
                s0[j] = fmaf(qa, kv, s0[j]);
                s1[j] = fmaf(qb, kv, s1[j]);
            }
        }
        #pragma unroll
        for (int j = 0; j < 4; j++) {
            int kpos = kt * 32 + tx * 4 + j;
            bool ok = (amask[b * S_ + kpos] != 0);
            float sa = s0[j] * scale, sb = s1[j] * scale;
            if (win >= 0) {
                int qa_ = q0 + r0, qb_ = q0 + r1;
                if (abs(qa_ - kpos) > win) sa = -1e30f;
                if (abs(qb_ - kpos) > win) sb = -1e30f;
            }
            if (!ok) { sa = -1e30f; sb = -1e30f; }
            s0[j] = sa; s1[j] = sb;
        }
        {
            float tm = fmaxf(fmaxf(s0[0], s0[1]), fmaxf(s0[2], s0[3]));
            #pragma unroll
            for (int o = 4; o; o >>= 1) tm = fmaxf(tm, __shfl_xor_sync(0xffffffffu, tm, o));
            float nm = fmaxf(m0, tm);
            float alpha = expf(m0 - nm);
            float ps = 0.f;
            #pragma unroll
            for (int j = 0; j < 4; j++) {
                float p = expf(s0[j] - nm);
                Ps[r0][tx * 4 + j] = p;
                ps += p;
            }
            #pragma unroll
            for (int o = 4; o; o >>= 1) ps += __shfl_xor_sync(0xffffffffu, ps, o);
            l0 = l0 * alpha + ps; m0 = nm;
            #pragma unroll
            for (int j = 0; j < 8; j++) o0[j] *= alpha;
        }
        {
            float tm = fmaxf(fmaxf(s1[0], s1[1]), fmaxf(s1[2], s1[3]));
            #pragma unroll
            for (int o = 4; o; o >>= 1) tm = fmaxf(tm, __shfl_xor_sync(0xffffffffu, tm, o));
            float nm = fmaxf(m1, tm);
            float alpha = expf(m1 - nm);
            float ps = 0.f;
            #pragma unroll
            for (int j = 0; j < 4; j++) {
                float p = expf(s1[j] - nm);
                Ps[r1][tx * 4 + j] = p;
                ps += p;
            }
            #pragma unroll
            for (int o = 4; o; o >>= 1) ps += __shfl_xor_sync(0xffffffffu, ps, o);
            l1 = l1 * alpha + ps; m1 = nm;
            #pragma unroll
            for (int j = 0; j < 8; j++) o1[j] *= alpha;
        }
        __syncthreads();
        #pragma unroll 4
        for (int kk = 0; kk < 32; kk++) {
            float p0 = Ps[r0][kk], p1 = Ps[r1][kk];
            #pragma unroll
            for (int j = 0; j < 8; j++) {
                float vv = Vs[kk][d0 + j];
                o0[j] = fmaf(p0, vv, o0[j]);
                o1[j] = fmaf(p1, vv, o1[j]);
            }
        }
        __syncthreads();
    }

    float il0 = 1.0f / l0, il1 = 1.0f / l1;
    size_t base0 = (size_t)(b * S_ + q0 + r0) * (H_ * HD_) + h * HD_ + d0;
    size_t base1 = (size_t)(b * S_ + q0 + r1) * (H_ * HD_) + h * HD_ + d0;
    #pragma unroll
    for (int j = 0; j < 8; j++) {
        out[base0 + j] = o0[j] * il0;
        out[base1 + j] = o1[j] * il1;
    }
}

// ---------------- SwiGLU elementwise: gate = silu(gate) * up ----------------
__global__ void silu_mul_kernel(float* __restrict__ gate,
                                const float* __restrict__ up, int n) {
    int i = blockIdx.x * blockDim.x + threadIdx.x;
    if (i < n) {
        float g = gate[i];
        float s = g / (1.0f + expf(-g));
        gate[i] = s * up[i];
    }
}

// ---------------- host orchestration ----------------
extern "C" void kernel_launch(void* const* d_in, const int* in_sizes, int n_in,
                              void* d_out, int out_size) {
    const float* x      = (const float*)d_in[0];
    const float* wq     = (const float*)d_in[1];
    const float* wk     = (const float*)d_in[2];
    const float* wv     = (const float*)d_in[3];
    const float* wo     = (const float*)d_in[4];
    const float* qnw    = (const float*)d_in[5];
    const float* knw    = (const float*)d_in[6];
    const float* ln1    = (const float*)d_in[7];
    const float* ln2    = (const float*)d_in[8];
    const float* wg     = (const float*)d_in[9];
    const float* wu     = (const float*)d_in[10];
    const float* wd     = (const float*)d_in[11];
    const float* normw  = (const float*)d_in[12];
    const int*   amask  = (const int*)d_in[13];

    float *h, *n, *q, *k, *v, *att, *gate, *up;
    cudaGetSymbolAddress((void**)&h,    g_h);
    cudaGetSymbolAddress((void**)&n,    g_n);
    cudaGetSymbolAddress((void**)&q,    g_q);
    cudaGetSymbolAddress((void**)&k,    g_k);
    cudaGetSymbolAddress((void**)&v,    g_v);
    cudaGetSymbolAddress((void**)&att,  g_att);
    cudaGetSymbolAddress((void**)&gate, g_gate);
    cudaGetSymbolAddress((void**)&up,   g_up);

    cudaMemcpyAsync(h, x, (size_t)TOK_ * D_ * sizeof(float),
                    cudaMemcpyDeviceToDevice, 0);

    dim3 g1024(D_ / 128, TOK_ / 128);
    dim3 g512 ((HK_ * HD_) / 128, TOK_ / 128);
    dim3 g3072(FF_ / 128, TOK_ / 128);

    for (int l = 0; l < L_; l++) {
        const float* wq_l = wq + (size_t)l * D_ * H_ * HD_;
        const float* wk_l = wk + (size_t)l * D_ * HK_ * HD_;
        const float* wv_l = wv + (size_t)l * D_ * HK_ * HD_;
        const float* wo_l = wo + (size_t)l * H_ * HD_ * D_;
        const float* wg_l = wg + (size_t)l * D_ * FF_;
        const float* wu_l = wu + (size_t)l * D_ * FF_;
        const float* wd_l = wd + (size_t)l * FF_ * D_;

        rmsnorm_kernel<<<TOK_, 256>>>(h, ln1 + l * D_, n);

        gemm_tf32<false><<<g1024, 256>>>(n, wq_l, q,  TOK_, H_  * HD_, D_);
        gemm_tf32<false><<<g512,  256>>>(n, wk_l, k,  TOK_, HK_ * HD_, D_);
        gemm_tf32<false><<<g512,  256>>>(n, wv_l, v,  TOK_, HK_ * HD_, D_);

        qknorm_rope_kernel<<<(TOK_ * H_)  / 4, 128>>>(q, qnw + l * HD_, H_);
        qknorm_rope_kernel<<<(TOK_ * HK_) / 4, 128>>>(k, knw + l * HD_, HK_);

        attn_kernel<<<dim3(S_ / 64, H_, B_), 256>>>(
            q, k, v, amask, att, (l & 1) ? WIN_ : -1);

        gemm_tf32<true><<<g1024, 256>>>(att, wo_l, h, TOK_, D_, H_ * HD_);

        rmsnorm_kernel<<<TOK_, 256>>>(h, ln2 + l * D_, n);

        gemm_tf32<false><<<g3072, 256>>>(n, wg_l, gate, TOK_, FF_, D_);
        gemm_tf32<false><<<g3072, 256>>>(n, wu_l, up,   TOK_, FF_, D_);

        int nel = TOK_ * FF_;
        silu_mul_kernel<<<(nel + 255) / 256, 256>>>(gate, up, nel);

        gemm_tf32<true><<<g1024, 256>>>(gate, wd_l, h, TOK_, D_, FF_);
    }

    rmsnorm_kernel<<<TOK_, 256>>>(h, normw, (float*)d_out);
}

// round 3
// speedup vs baseline: 1.7288x; 1.0508x over previous
#include <cuda_runtime.h>
#include <math.h>
#include <float.h>

#define D_    1024
#define H_    16
#define HK_   8
#define HD_   64
#define FF_   3072
#define S_    1024
#define B_    4
#define TOK_  4096   // B*S
#define L_    4
#define WIN_  12

// ---------------- scratch (no allocations allowed) ----------------
__device__ float g_h   [TOK_ * D_];
__device__ float g_n   [TOK_ * D_];
__device__ float g_q   [TOK_ * H_  * HD_];
__device__ float g_k   [TOK_ * HK_ * HD_];
__device__ float g_v   [TOK_ * HK_ * HD_];
__device__ float g_att [TOK_ * H_  * HD_];
__device__ float g_gate[TOK_ * FF_];
__device__ float g_up  [TOK_ * FF_];

// ---------------- rmsnorm over 1024 cols, 1 block per row ----------------
__global__ void rmsnorm_kernel(const float* __restrict__ x,
                               const float* __restrict__ w,
                               float* __restrict__ out) {
    int row = blockIdx.x;
    const float* xr = x + (size_t)row * D_;
    int t = threadIdx.x;               // 256 threads, 4 floats each
    float4 v = *(const float4*)(xr + t * 4);
    float ss = v.x * v.x + v.y * v.y + v.z * v.z + v.w * v.w;
    #pragma unroll
    for (int o = 16; o; o >>= 1) ss += __shfl_xor_sync(0xffffffffu, ss, o);
    __shared__ float sh[8];
    if ((t & 31) == 0) sh[t >> 5] = ss;
    __syncthreads();
    float tot = 0.f;
    #pragma unroll
    for (int i = 0; i < 8; i++) tot += sh[i];
    float scale = rsqrtf(tot * (1.0f / D_) + 1e-6f);
    float4 wv = *(const float4*)(w + t * 4);
    float4 o4;
    o4.x = v.x * scale * wv.x;
    o4.y = v.y * scale * wv.y;
    o4.z = v.z * scale * wv.z;
    o4.w = v.w * scale * wv.w;
    *(float4*)(out + (size_t)row * D_ + t * 4) = o4;
}

// ---------------- tf32 → bits helper (round-to-nearest) ----------------
__device__ __forceinline__ unsigned f2tf(float x) {
    unsigned r;
    asm("cvt.rna.tf32.f32 %0, %1;" : "=r"(r) : "f"(x));
    return r;
}

// ---------------- TF32 tensor-core GEMM core: C[.,N] (+)= A[.,K] @ B[K,N] ----------------
// Tile 128x128, BK=16, 256 threads (8 warps, 2x4). Warp tile 64x32 via 4x4 m16n8k8.
template <bool ACC>
__device__ __forceinline__ void gemm_core(const float* __restrict__ A,
                                          const float* __restrict__ B,
                                          float* __restrict__ C,
                                          int N, int K, int bx, int by) {
    __shared__ unsigned As[2][16][136];
    __shared__ unsigned Bs[2][16][136];

    int tid = threadIdx.x;
    int lane = tid & 31, wid = tid >> 5;
    int wr = wid >> 2;          // 0..1  (64-row slab)
    int wc = wid & 3;           // 0..3  (32-col slab)
    int tg = lane & 3;          // thread-in-group (k index)
    int grp = lane >> 2;        // group (m/n index)

    const float* Ag = A + (size_t)(by * 128) * K;
    const float* Bg = B + bx * 128;

    int af0 = tid * 2, af1 = tid * 2 + 1;
    int ar0 = af0 >> 2, ac0 = (af0 & 3) << 2;
    int ar1 = af1 >> 2, ac1 = (af1 & 3) << 2;
    int br0 = af0 >> 5, bc0 = (af0 & 31) << 2;
    int br1 = af1 >> 5, bc1 = (af1 & 31) << 2;

    float acc[4][4][4];
    #pragma unroll
    for (int i = 0; i < 4; i++)
        #pragma unroll
        for (int j = 0; j < 4; j++)
            #pragma unroll
            for (int c = 0; c < 4; c++) acc[i][j][c] = 0.f;

    float4 a0g, a1g, b0g, b1g;

    a0g = *(const float4*)(Ag + (size_t)ar0 * K + ac0);
    a1g = *(const float4*)(Ag + (size_t)ar1 * K + ac1);
    b0g = *(const float4*)(Bg + (size_t)br0 * N + bc0);
    b1g = *(const float4*)(Bg + (size_t)br1 * N + bc1);
    {
        As[0][ac0 + 0][ar0] = f2tf(a0g.x); As[0][ac0 + 1][ar0] = f2tf(a0g.y);
        As[0][ac0 + 2][ar0] = f2tf(a0g.z); As[0][ac0 + 3][ar0] = f2tf(a0g.w);
        As[0][ac1 + 0][ar1] = f2tf(a1g.x); As[0][ac1 + 1][ar1] = f2tf(a1g.y);
        As[0][ac1 + 2][ar1] = f2tf(a1g.z); As[0][ac1 + 3][ar1] = f2tf(a1g.w);
        uint4 u0 = make_uint4(f2tf(b0g.x), f2tf(b0g.y), f2tf(b0g.z), f2tf(b0g.w));
        uint4 u1 = make_uint4(f2tf(b1g.x), f2tf(b1g.y), f2tf(b1g.z), f2tf(b1g.w));
        *(uint4*)&Bs[0][br0][bc0] = u0;
        *(uint4*)&Bs[0][br1][bc1] = u1;
    }
    __syncthreads();

    int nIter = K >> 4;
    int cur = 0;
    for (int it = 0; it < nIter; it++) {
        int k0n = (it + 1) << 4;
        bool hasNext = (it + 1) < nIter;
        if (hasNext) {
            a0g = *(const float4*)(Ag + (size_t)ar0 * K + k0n + ac0);
            a1g = *(const float4*)(Ag + (size_t)ar1 * K + k0n + ac1);
            b0g = *(const float4*)(Bg + (size_t)(k0n + br0) * N + bc0);
            b1g = *(const float4*)(Bg + (size_t)(k0n + br1) * N + bc1);
        }

        #pragma unroll
        for (int kk = 0; kk < 16; kk += 8) {
            unsigned afr[4][4], bfr[4][2];
            #pragma unroll
            for (int mt = 0; mt < 4; mt++) {
                int m = wr * 64 + mt * 16 + grp;
                afr[mt][0] = As[cur][kk + tg][m];
                afr[mt][1] = As[cur][kk + tg][m + 8];
                afr[mt][2] = As[cur][kk + tg + 4][m];
                afr[mt][3] = As[cur][kk + tg + 4][m + 8];
            }
            #pragma unroll
            for (int nt = 0; nt < 4; nt++) {
                int n = wc * 32 + nt * 8 + grp;
                bfr[nt][0] = Bs[cur][kk + tg][n];
                bfr[nt][1] = Bs[cur][kk + tg + 4][n];
            }
            #pragma unroll
            for (int mt = 0; mt < 4; mt++)
                #pragma unroll
                for (int nt = 0; nt < 4; nt++) {
                    asm volatile(
                        "mma.sync.aligned.m16n8k8.row.col.f32.tf32.tf32.f32 "
                        "{%0,%1,%2,%3}, {%4,%5,%6,%7}, {%8,%9}, {%0,%1,%2,%3};"
                        : "+f"(acc[mt][nt][0]), "+f"(acc[mt][nt][1]),
                          "+f"(acc[mt][nt][2]), "+f"(acc[mt][nt][3])
                        : "r"(afr[mt][0]), "r"(afr[mt][1]),
                          "r"(afr[mt][2]), "r"(afr[mt][3]),
                          "r"(bfr[nt][0]), "r"(bfr[nt][1]));
                }
        }

        if (hasNext) {
            int nxt = cur ^ 1;
            As[nxt][ac0 + 0][ar0] = f2tf(a0g.x); As[nxt][ac0 + 1][ar0] = f2tf(a0g.y);
            As[nxt][ac0 + 2][ar0] = f2tf(a0g.z); As[nxt][ac0 + 3][ar0] = f2tf(a0g.w);
            As[nxt][ac1 + 0][ar1] = f2tf(a1g.x); As[nxt][ac1 + 1][ar1] = f2tf(a1g.y);
            As[nxt][ac1 + 2][ar1] = f2tf(a1g.z); As[nxt][ac1 + 3][ar1] = f2tf(a1g.w);
            uint4 u0 = make_uint4(f2tf(b0g.x), f2tf(b0g.y), f2tf(b0g.z), f2tf(b0g.w));
            uint4 u1 = make_uint4(f2tf(b1g.x), f2tf(b1g.y), f2tf(b1g.z), f2tf(b1g.w));
            *(uint4*)&Bs[nxt][br0][bc0] = u0;
            *(uint4*)&Bs[nxt][br1][bc1] = u1;
            __syncthreads();
            cur = nxt;
        }
    }

    #pragma unroll
    for (int mt = 0; mt < 4; mt++) {
        int row0 = by * 128 + wr * 64 + mt * 16 + grp;
        #pragma unroll
        for (int nt = 0; nt < 4; nt++) {
            int col = bx * 128 + wc * 32 + nt * 8 + tg * 2;
            float* p0 = C + (size_t)row0 * N + col;
            float* p1 = C + (size_t)(row0 + 8) * N + col;
            if (ACC) {
                float2 c0 = *(float2*)p0, c1 = *(float2*)p1;
                c0.x += acc[mt][nt][0]; c0.y += acc[mt][nt][1];
                c1.x += acc[mt][nt][2]; c1.y += acc[mt][nt][3];
                *(float2*)p0 = c0; *(float2*)p1 = c1;
            } else {
                *(float2*)p0 = make_float2(acc[mt][nt][0], acc[mt][nt][1]);
                *(float2*)p1 = make_float2(acc[mt][nt][2], acc[mt][nt][3]);
            }
        }
    }
}

// plain single-matrix GEMM
template <bool ACC>
__global__ void __launch_bounds__(256, 2)
gemm_tf32(const float* __restrict__ A, const float* __restrict__ B,
          float* __restrict__ C, int N, int K) {
    gemm_core<ACC>(A, B, C, N, K, blockIdx.x, blockIdx.y);
}

// fused QKV: bx 0..7 -> q (N=1024), 8..11 -> k (N=512), 12..15 -> v (N=512)
__global__ void __launch_bounds__(256, 2)
gemm_qkv(const float* __restrict__ A,
         const float* __restrict__ Wq, const float* __restrict__ Wk,
         const float* __restrict__ Wv,
         float* __restrict__ q, float* __restrict__ k, float* __restrict__ v) {
    int bx = blockIdx.x;
    if (bx < 8)       gemm_core<false>(A, Wq, q, 1024, D_, bx,      blockIdx.y);
    else if (bx < 12) gemm_core<false>(A, Wk, k,  512, D_, bx - 8,  blockIdx.y);
    else              gemm_core<false>(A, Wv, v,  512, D_, bx - 12, blockIdx.y);
}

// fused gate+up: bx 0..23 -> gate, 24..47 -> up (both N=3072)
__global__ void __launch_bounds__(256, 2)
gemm_gateup(const float* __restrict__ A,
            const float* __restrict__ Wg, const float* __restrict__ Wu,
            float* __restrict__ gate, float* __restrict__ up) {
    int bx = blockIdx.x;
    if (bx < 24) gemm_core<false>(A, Wg, gate, FF_, D_, bx,      blockIdx.y);
    else         gemm_core<false>(A, Wu, up,   FF_, D_, bx - 24, blockIdx.y);
}

// ---------------- per-head rmsnorm + RoPE (one warp per (token, head)) ----------------
__global__ void qknorm_rope_kernel(float* __restrict__ x,
                                   const float* __restrict__ w, int nh) {
    int warp = (blockIdx.x * blockDim.x + threadIdx.x) >> 5;
    int lane = threadIdx.x & 31;
    int token = warp / nh;
    int s = token & (S_ - 1);          // position within sequence
    float* p = x + (size_t)warp * HD_;
    float a = p[lane], b = p[lane + 32];
    float ss = a * a + b * b;
    #pragma unroll
    for (int o = 16; o; o >>= 1) ss += __shfl_xor_sync(0xffffffffu, ss, o);
    float scale = rsqrtf(ss * (1.0f / HD_) + 1e-6f);
    a *= scale * w[lane];
    b *= scale * w[lane + 32];
    float inv = (float)(1.0 / pow(1000000.0, (double)lane / 32.0));
    float ang = (float)s * inv;
    float c = cosf(ang), sn = sinf(ang);
    p[lane]      = a * c - b * sn;
    p[lane + 32] = b * c + a * sn;
}

// ---------------- flash attention: block = (b, h, 64 q rows), K-tile 32 ----------------
__global__ void __launch_bounds__(256)
attn_kernel(const float* __restrict__ q, const float* __restrict__ k,
            const float* __restrict__ v, const int* __restrict__ amask,
            float* __restrict__ out, int win) {
    __shared__ float Qs[64][65];
    __shared__ float Ks[32][65];
    __shared__ float Vs[32][64];
    __shared__ float Ps[64][33];

    int b = blockIdx.z, h = blockIdx.y;
    int q0 = blockIdx.x * 64;
    int kh = h >> 1;                       // GQA: 2 q-heads per kv-head
    int tid = threadIdx.x;
    int tx = tid & 7;
    int tyg = tid >> 3;
    int r0 = tyg * 2, r1 = r0 + 1;
    int d0 = tx * 8;

    for (int i = tid; i < 64 * 16; i += 256) {
        int r = i >> 4, c4 = (i & 15) << 2;
        float4 f = *(const float4*)(q + ((size_t)(b * S_ + q0 + r) * (H_ * HD_)) + h * HD_ + c4);
        Qs[r][c4] = f.x; Qs[r][c4 + 1] = f.y; Qs[r][c4 + 2] = f.z; Qs[r][c4 + 3] = f.w;
    }

    float m0 = -1e30f, m1 = -1e30f, l0 = 0.f, l1 = 0.f;
    float o0[8], o1[8];
    #pragma unroll
    for (int j = 0; j < 8; j++) { o0[j] = 0.f; o1[j] = 0.f; }

    int kt_lo = 0, kt_hi = (S_ / 32) - 1;
    if (win >= 0) {
        int lo = q0 - win; if (lo < 0) lo = 0;
        int hi = q0 + 63 + win; if (hi > S_ - 1) hi = S_ - 1;
        kt_lo = lo >> 5; kt_hi = hi >> 5;
    }
    const float scale = 0.125f;

    __syncthreads();
    for (int kt = kt_lo; kt <= kt_hi; kt++) {
        int kbase = b * S_ + kt * 32;
        for (int i = tid; i < 32 * 16; i += 256) {
            int r = i >> 4, c4 = (i & 15) << 2;
            size_t off = (size_t)(kbase + r) * (HK_ * HD_) + kh * HD_ + c4;
            float4 fk = *(const float4*)(k + off);
            float4 fv = *(const float4*)(v + off);
            Ks[r][c4] = fk.x; Ks[r][c4 + 1] = fk.y; Ks[r][c4 + 2] = fk.z; Ks[r][c4 + 3] = fk.w;
            *(float4*)&Vs[r][c4] = fv;
        }
        __syncthreads();

        float s0[4], s1[4];
        #pragma unroll
        for (int j = 0; j < 4; j++) { s0[j] = 0.f; s1[j] = 0.f; }
        #pragma unroll 8
        for (int d = 0; d < 64; d++) {
            float qa = Qs[r0][d], qb = Qs[r1][d];
            #pragma unroll
            for (int j = 0; j < 4; j++) {
                float kv = Ks[tx * 4 + j][d];
                s0[j] = fmaf(qa, kv, s0[j]);
                s1[j] = fmaf(qb, kv, s1[j]);
            }
        }
        #pragma unroll
        for (int j = 0; j < 4; j++) {
            int kpos = kt * 32 + tx * 4 + j;
            bool ok = (amask[b * S_ + kpos] != 0);
            float sa = s0[j] * scale, sb = s1[j] * scale;
            if (win >= 0) {
                int qa_ = q0 + r0, qb_ = q0 + r1;
                if (abs(qa_ - kpos) > win) sa = -1e30f;
                if (abs(qb_ - kpos) > win) sb = -1e30f;
            }
            if (!ok) { sa = -1e30f; sb = -1e30f; }
            s0[j] = sa; s1[j] = sb;
        }
        {
            float tm = fmaxf(fmaxf(s0[0], s0[1]), fmaxf(s0[2], s0[3]));
            #pragma unroll
            for (int o = 4; o; o >>= 1) tm = fmaxf(tm, __shfl_xor_sync(0xffffffffu, tm, o));
            float nm = fmaxf(m0, tm);
            float alpha = expf(m0 - nm);
            float ps = 0.f;
            #pragma unroll
            for (int j = 0; j < 4; j++) {
                float p = expf(s0[j] - nm);
                Ps[r0][tx * 4 + j] = p;
                ps += p;
            }
            #pragma unroll
            for (int o = 4; o; o >>= 1) ps += __shfl_xor_sync(0xffffffffu, ps, o);
            l0 = l0 * alpha + ps; m0 = nm;
            #pragma unroll
            for (int j = 0; j < 8; j++) o0[j] *= alpha;
        }
        {
            float tm = fmaxf(fmaxf(s1[0], s1[1]), fmaxf(s1[2], s1[3]));
            #pragma unroll
            for (int o = 4; o; o >>= 1) tm = fmaxf(tm, __shfl_xor_sync(0xffffffffu, tm, o));
            float nm = fmaxf(m1, tm);
            float alpha = expf(m1 - nm);
            float ps = 0.f;
            #pragma unroll
            for (int j = 0; j < 4; j++) {
                float p = expf(s1[j] - nm);
                Ps[r1][tx * 4 + j] = p;
                ps += p;
            }
            #pragma unroll
            for (int o = 4; o; o >>= 1) ps += __shfl_xor_sync(0xffffffffu, ps, o);
            l1 = l1 * alpha + ps; m1 = nm;
            #pragma unroll
            for (int j = 0; j < 8; j++) o1[j] *= alpha;
        }
        __syncthreads();
        #pragma unroll 4
        for (int kk = 0; kk < 32; kk++) {
            float p0 = Ps[r0][kk], p1 = Ps[r1][kk];
            #pragma unroll
            for (int j = 0; j < 8; j++) {
                float vv = Vs[kk][d0 + j];
                o0[j] = fmaf(p0, vv, o0[j]);
                o1[j] = fmaf(p1, vv, o1[j]);
            }
        }
        __syncthreads();
    }

    float il0 = 1.0f / l0, il1 = 1.0f / l1;
    size_t base0 = (size_t)(b * S_ + q0 + r0) * (H_ * HD_) + h * HD_ + d0;
    size_t base1 = (size_t)(b * S_ + q0 + r1) * (H_ * HD_) + h * HD_ + d0;
    #pragma unroll
    for (int j = 0; j < 8; j++) {
        out[base0 + j] = o0[j] * il0;
        out[base1 + j] = o1[j] * il1;
    }
}

// ---------------- SwiGLU elementwise: gate = silu(gate) * up ----------------
__global__ void silu_mul_kernel(float* __restrict__ gate,
                                const float* __restrict__ up, int n) {
    int i = blockIdx.x * blockDim.x + threadIdx.x;
    if (i < n) {
        float g = gate[i];
        float s = g / (1.0f + expf(-g));
        gate[i] = s * up[i];
    }
}

// ---------------- host orchestration ----------------
extern "C" void kernel_launch(void* const* d_in, const int* in_sizes, int n_in,
                              void* d_out, int out_size) {
    const float* x      = (const float*)d_in[0];
    const float* wq     = (const float*)d_in[1];
    const float* wk     = (const float*)d_in[2];
    const float* wv     = (const float*)d_in[3];
    const float* wo     = (const float*)d_in[4];
    const float* qnw    = (const float*)d_in[5];
    const float* knw    = (const float*)d_in[6];
    const float* ln1    = (const float*)d_in[7];
    const float* ln2    = (const float*)d_in[8];
    const float* wg     = (const float*)d_in[9];
    const float* wu     = (const float*)d_in[10];
    const float* wd     = (const float*)d_in[11];
    const float* normw  = (const float*)d_in[12];
    const int*   amask  = (const int*)d_in[13];

    float *h, *n, *q, *k, *v, *att, *gate, *up;
    cudaGetSymbolAddress((void**)&h,    g_h);
    cudaGetSymbolAddress((void**)&n,    g_n);
    cudaGetSymbolAddress((void**)&q,    g_q);
    cudaGetSymbolAddress((void**)&k,    g_k);
    cudaGetSymbolAddress((void**)&v,    g_v);
    cudaGetSymbolAddress((void**)&att,  g_att);
    cudaGetSymbolAddress((void**)&gate, g_gate);
    cudaGetSymbolAddress((void**)&up,   g_up);

    cudaMemcpyAsync(h, x, (size_t)TOK_ * D_ * sizeof(float),
                    cudaMemcpyDeviceToDevice, 0);

    dim3 gQKV (16, TOK_ / 128);              // 512 blocks
    dim3 gGU  (48, TOK_ / 128);              // 1536 blocks
    dim3 g1024(D_ / 128, TOK_ / 128);        // 256 blocks

    for (int l = 0; l < L_; l++) {
        const float* wq_l = wq + (size_t)l * D_ * H_ * HD_;
        const float* wk_l = wk + (size_t)l * D_ * HK_ * HD_;
        const float* wv_l = wv + (size_t)l * D_ * HK_ * HD_;
        const float* wo_l = wo + (size_t)l * H_ * HD_ * D_;
        const float* wg_l = wg + (size_t)l * D_ * FF_;
        const float* wu_l = wu + (size_t)l * D_ * FF_;
        const float* wd_l = wd + (size_t)l * FF_ * D_;

        rmsnorm_kernel<<<TOK_, 256>>>(h, ln1 + l * D_, n);

        gemm_qkv<<<gQKV, 256>>>(n, wq_l, wk_l, wv_l, q, k, v);

        qknorm_rope_kernel<<<(TOK_ * H_)  / 4, 128>>>(q, qnw + l * HD_, H_);
        qknorm_rope_kernel<<<(TOK_ * HK_) / 4, 128>>>(k, knw + l * HD_, HK_);

        attn_kernel<<<dim3(S_ / 64, H_, B_), 256>>>(
            q, k, v, amask, att, (l & 1) ? WIN_ : -1);

        gemm_tf32<true><<<g1024, 256>>>(att, wo_l, h, D_, H_ * HD_);

        rmsnorm_kernel<<<TOK_, 256>>>(h, ln2 + l * D_, n);

        gemm_gateup<<<gGU, 256>>>(n, wg_l, wu_l, gate, up);

        int nel = TOK_ * FF_;
        silu_mul_kernel<<<(nel + 255) / 256, 256>>>(gate, up, nel);

        gemm_tf32<true><<<g1024, 256>>>(gate, wd_l, h, D_, FF_);
    }

    rmsnorm_kernel<<<TOK_, 256>>>(h, normw, (float*)d_out);
}

// round 4
// speedup vs baseline: 2.4688x; 1.4281x over previous
#include <cuda_runtime.h>
#include <math.h>
#include <float.h>

#define D_    1024
#define H_    16
#define HK_   8
#define HD_   64
#define FF_   3072
#define S_    1024
#define B_    4
#define TOK_  4096   // B*S
#define L_    4
#define WIN_  12

// ---------------- scratch (no allocations allowed) ----------------
__device__ float g_h   [TOK_ * D_];
__device__ float g_n   [TOK_ * D_];
__device__ float g_q   [TOK_ * H_  * HD_];
__device__ float g_k   [TOK_ * HK_ * HD_];
__device__ float g_v   [TOK_ * HK_ * HD_];
__device__ float g_att [TOK_ * H_  * HD_];
__device__ float g_gate[TOK_ * FF_];
__device__ float g_up  [TOK_ * FF_];

// ---------------- rmsnorm over 1024 cols, 1 block per row ----------------
__global__ void rmsnorm_kernel(const float* __restrict__ x,
                               const float* __restrict__ w,
                               float* __restrict__ out) {
    int row = blockIdx.x;
    const float* xr = x + (size_t)row * D_;
    int t = threadIdx.x;               // 256 threads, 4 floats each
    float4 v = *(const float4*)(xr + t * 4);
    float ss = v.x * v.x + v.y * v.y + v.z * v.z + v.w * v.w;
    #pragma unroll
    for (int o = 16; o; o >>= 1) ss += __shfl_xor_sync(0xffffffffu, ss, o);
    __shared__ float sh[8];
    if ((t & 31) == 0) sh[t >> 5] = ss;
    __syncthreads();
    float tot = 0.f;
    #pragma unroll
    for (int i = 0; i < 8; i++) tot += sh[i];
    float scale = rsqrtf(tot * (1.0f / D_) + 1e-6f);
    float4 wv = *(const float4*)(w + t * 4);
    float4 o4;
    o4.x = v.x * scale * wv.x;
    o4.y = v.y * scale * wv.y;
    o4.z = v.z * scale * wv.z;
    o4.w = v.w * scale * wv.w;
    *(float4*)(out + (size_t)row * D_ + t * 4) = o4;
}

// ---------------- helpers ----------------
__device__ __forceinline__ unsigned f2tf(float x) {
    unsigned r;
    asm("cvt.rna.tf32.f32 %0, %1;" : "=r"(r) : "f"(x));
    return r;
}
__device__ __forceinline__ void cpasync16(float* dst_smem, const float* src_gmem) {
    unsigned d = (unsigned)__cvta_generic_to_shared(dst_smem);
    asm volatile("cp.async.cg.shared.global [%0], [%1], 16;"
                 :: "r"(d), "l"(src_gmem));
}
#define CP_COMMIT() asm volatile("cp.async.commit_group;")
#define CP_WAIT0()  asm volatile("cp.async.wait_group 0;")

// ---------------- TF32 tensor-core GEMM core (cp.async pipelined) ----------------
// Tile 128x128, BK=16, 2-stage cp.async. 256 threads (8 warps, 2x4).
// A smem row-major stride 20 (conflict-free), B smem stride 136.
#define AST_ 20
#define BST_ 136
template <bool ACC>
__device__ __forceinline__ void gemm_core(const float* __restrict__ A,
                                          const float* __restrict__ B,
                                          float* __restrict__ C,
                                          int N, int K, int bx, int by) {
    __shared__ float As[2][128 * AST_];
    __shared__ float Bs[2][16 * BST_];

    int tid = threadIdx.x;
    int lane = tid & 31, wid = tid >> 5;
    int wr = wid >> 2;          // 0..1  (64-row slab)
    int wc = wid & 3;           // 0..3  (32-col slab)
    int tg = lane & 3;          // k index within fragment
    int grp = lane >> 2;        // m/n index within fragment

    const float* Ag = A + (size_t)(by * 128) * K;
    const float* Bg = B + bx * 128;

    // cp.async plan: 2 x 16B chunks per thread for each of A and B
    int c0 = tid * 2, c1 = tid * 2 + 1;
    int ar0 = c0 >> 2, ac0 = (c0 & 3) << 2;
    int ar1 = c1 >> 2, ac1 = (c1 & 3) << 2;
    int br0 = c0 >> 5, bc0 = (c0 & 31) << 2;
    int br1 = c1 >> 5, bc1 = (c1 & 31) << 2;

    float acc[4][4][4];
    #pragma unroll
    for (int i = 0; i < 4; i++)
        #pragma unroll
        for (int j = 0; j < 4; j++)
            #pragma unroll
            for (int c = 0; c < 4; c++) acc[i][j][c] = 0.f;

    // prologue: stage 0
    cpasync16(&As[0][ar0 * AST_ + ac0], Ag + (size_t)ar0 * K + ac0);
    cpasync16(&As[0][ar1 * AST_ + ac1], Ag + (size_t)ar1 * K + ac1);
    cpasync16(&Bs[0][br0 * BST_ + bc0], Bg + (size_t)br0 * N + bc0);
    cpasync16(&Bs[0][br1 * BST_ + bc1], Bg + (size_t)br1 * N + bc1);
    CP_COMMIT();

    int nIter = K >> 4;
    for (int it = 0; it < nIter; it++) {
        int cur = it & 1;
        CP_WAIT0();
        __syncthreads();
        // issue next stage (overlaps with compute below)
        if (it + 1 < nIter) {
            int nxt = cur ^ 1;
            int k0n = (it + 1) << 4;
            cpasync16(&As[nxt][ar0 * AST_ + ac0], Ag + (size_t)ar0 * K + k0n + ac0);
            cpasync16(&As[nxt][ar1 * AST_ + ac1], Ag + (size_t)ar1 * K + k0n + ac1);
            cpasync16(&Bs[nxt][br0 * BST_ + bc0], Bg + (size_t)(k0n + br0) * N + bc0);
            cpasync16(&Bs[nxt][br1 * BST_ + bc1], Bg + (size_t)(k0n + br1) * N + bc1);
            CP_COMMIT();
        }

        #pragma unroll
        for (int kk = 0; kk < 16; kk += 8) {
            unsigned afr[4][4], bfr[4][2];
            #pragma unroll
            for (int mt = 0; mt < 4; mt++) {
                int m = wr * 64 + mt * 16 + grp;
                afr[mt][0] = f2tf(As[cur][m * AST_ + kk + tg]);
                afr[mt][1] = f2tf(As[cur][(m + 8) * AST_ + kk + tg]);
                afr[mt][2] = f2tf(As[cur][m * AST_ + kk + tg + 4]);
                afr[mt][3] = f2tf(As[cur][(m + 8) * AST_ + kk + tg + 4]);
            }
            #pragma unroll
            for (int nt = 0; nt < 4; nt++) {
                int n = wc * 32 + nt * 8 + grp;
                bfr[nt][0] = f2tf(Bs[cur][(kk + tg) * BST_ + n]);
                bfr[nt][1] = f2tf(Bs[cur][(kk + tg + 4) * BST_ + n]);
            }
            #pragma unroll
            for (int mt = 0; mt < 4; mt++)
                #pragma unroll
                for (int nt = 0; nt < 4; nt++) {
                    asm volatile(
                        "mma.sync.aligned.m16n8k8.row.col.f32.tf32.tf32.f32 "
                        "{%0,%1,%2,%3}, {%4,%5,%6,%7}, {%8,%9}, {%0,%1,%2,%3};"
                        : "+f"(acc[mt][nt][0]), "+f"(acc[mt][nt][1]),
                          "+f"(acc[mt][nt][2]), "+f"(acc[mt][nt][3])
                        : "r"(afr[mt][0]), "r"(afr[mt][1]),
                          "r"(afr[mt][2]), "r"(afr[mt][3]),
                          "r"(bfr[nt][0]), "r"(bfr[nt][1]));
                }
        }
        __syncthreads();
    }

    #pragma unroll
    for (int mt = 0; mt < 4; mt++) {
        int row0 = by * 128 + wr * 64 + mt * 16 + grp;
        #pragma unroll
        for (int nt = 0; nt < 4; nt++) {
            int col = bx * 128 + wc * 32 + nt * 8 + tg * 2;
            float* p0 = C + (size_t)row0 * N + col;
            float* p1 = C + (size_t)(row0 + 8) * N + col;
            if (ACC) {
                float2 cc0 = *(float2*)p0, cc1 = *(float2*)p1;
                cc0.x += acc[mt][nt][0]; cc0.y += acc[mt][nt][1];
                cc1.x += acc[mt][nt][2]; cc1.y += acc[mt][nt][3];
                *(float2*)p0 = cc0; *(float2*)p1 = cc1;
            } else {
                *(float2*)p0 = make_float2(acc[mt][nt][0], acc[mt][nt][1]);
                *(float2*)p1 = make_float2(acc[mt][nt][2], acc[mt][nt][3]);
            }
        }
    }
}

template <bool ACC>
__global__ void __launch_bounds__(256, 2)
gemm_tf32(const float* __restrict__ A, const float* __restrict__ B,
          float* __restrict__ C, int N, int K) {
    gemm_core<ACC>(A, B, C, N, K, blockIdx.x, blockIdx.y);
}

// fused QKV: bx 0..7 -> q (N=1024), 8..11 -> k (N=512), 12..15 -> v (N=512)
__global__ void __launch_bounds__(256, 2)
gemm_qkv(const float* __restrict__ A,
         const float* __restrict__ Wq, const float* __restrict__ Wk,
         const float* __restrict__ Wv,
         float* __restrict__ q, float* __restrict__ k, float* __restrict__ v) {
    int bx = blockIdx.x;
    if (bx < 8)       gemm_core<false>(A, Wq, q, 1024, D_, bx,      blockIdx.y);
    else if (bx < 12) gemm_core<false>(A, Wk, k,  512, D_, bx - 8,  blockIdx.y);
    else              gemm_core<false>(A, Wv, v,  512, D_, bx - 12, blockIdx.y);
}

// fused gate+up: bx 0..23 -> gate, 24..47 -> up (both N=3072)
__global__ void __launch_bounds__(256, 2)
gemm_gateup(const float* __restrict__ A,
            const float* __restrict__ Wg, const float* __restrict__ Wu,
            float* __restrict__ gate, float* __restrict__ up) {
    int bx = blockIdx.x;
    if (bx < 24) gemm_core<false>(A, Wg, gate, FF_, D_, bx,      blockIdx.y);
    else         gemm_core<false>(A, Wu, up,   FF_, D_, bx - 24, blockIdx.y);
}

// ---------------- per-head rmsnorm + RoPE (one warp per (token, head)) ----------------
// log2(1e6) for exp2f-based inv_freq (no FP64!)
#define LOG2_THETA 19.9315685693241741f
__global__ void qknorm_rope_kernel(float* __restrict__ x,
                                   const float* __restrict__ w, int nh) {
    int warp = (blockIdx.x * blockDim.x + threadIdx.x) >> 5;
    int lane = threadIdx.x & 31;
    int token = warp / nh;
    int s = token & (S_ - 1);          // position within sequence
    float* p = x + (size_t)warp * HD_;
    float a = p[lane], b = p[lane + 32];
    float ss = a * a + b * b;
    #pragma unroll
    for (int o = 16; o; o >>= 1) ss += __shfl_xor_sync(0xffffffffu, ss, o);
    float scale = rsqrtf(ss * (1.0f / HD_) + 1e-6f);
    a *= scale * w[lane];
    b *= scale * w[lane + 32];
    float inv = exp2f(-(float)lane * (LOG2_THETA / 32.0f));
    float ang = (float)s * inv;
    float c = cosf(ang), sn = sinf(ang);
    p[lane]      = a * c - b * sn;
    p[lane + 32] = b * c + a * sn;
}

// ---------------- flash attention: block = (b, h, 64 q rows), K-tile 32 ----------------
__global__ void __launch_bounds__(256)
attn_kernel(const float* __restrict__ q, const float* __restrict__ k,
            const float* __restrict__ v, const int* __restrict__ amask,
            float* __restrict__ out, int win) {
    __shared__ float Qs[64][65];
    __shared__ float Ks[32][65];
    __shared__ float Vs[32][64];
    __shared__ float Ps[64][33];

    int b = blockIdx.z, h = blockIdx.y;
    int q0 = blockIdx.x * 64;
    int kh = h >> 1;                       // GQA: 2 q-heads per kv-head
    int tid = threadIdx.x;
    int tx = tid & 7;
    int tyg = tid >> 3;
    int r0 = tyg * 2, r1 = r0 + 1;
    int d0 = tx * 8;

    for (int i = tid; i < 64 * 16; i += 256) {
        int r = i >> 4, c4 = (i & 15) << 2;
        float4 f = *(const float4*)(q + ((size_t)(b * S_ + q0 + r) * (H_ * HD_)) + h * HD_ + c4);
        Qs[r][c4] = f.x; Qs[r][c4 + 1] = f.y; Qs[r][c4 + 2] = f.z; Qs[r][c4 + 3] = f.w;
    }

    float m0 = -1e30f, m1 = -1e30f, l0 = 0.f, l1 = 0.f;
    float o0[8], o1[8];
    #pragma unroll
    for (int j = 0; j < 8; j++) { o0[j] = 0.f; o1[j] = 0.f; }

    int kt_lo = 0, kt_hi = (S_ / 32) - 1;
    if (win >= 0) {
        int lo = q0 - win; if (lo < 0) lo = 0;
        int hi = q0 + 63 + win; if (hi > S_ - 1) hi = S_ - 1;
        kt_lo = lo >> 5; kt_hi = hi >> 5;
    }
    const float scale = 0.125f;

    __syncthreads();
    for (int kt = kt_lo; kt <= kt_hi; kt++) {
        int kbase = b * S_ + kt * 32;
        for (int i = tid; i < 32 * 16; i += 256) {
            int r = i >> 4, c4 = (i & 15) << 2;
            size_t off = (size_t)(kbase + r) * (HK_ * HD_) + kh * HD_ + c4;
            float4 fk = *(const float4*)(k + off);
            float4 fv = *(const float4*)(v + off);
            Ks[r][c4] = fk.x; Ks[r][c4 + 1] = fk.y; Ks[r][c4 + 2] = fk.z; Ks[r][c4 + 3] = fk.w;
            *(float4*)&Vs[r][c4] = fv;
        }
        __syncthreads();

        float s0[4], s1[4];
        #pragma unroll
        for (int j = 0; j < 4; j++) { s0[j] = 0.f; s1[j] = 0.f; }
        #pragma unroll 8
        for (int d = 0; d < 64; d++) {
            float qa = Qs[r0][d], qb = Qs[r1][d];
            #pragma unroll
            for (int j = 0; j < 4; j++) {
                float kv = Ks[tx * 4 + j][d];
                s0[j] = fmaf(qa, kv, s0[j]);
                s1[j] = fmaf(qb, kv, s1[j]);
            }
        }
        #pragma unroll
        for (int j = 0; j < 4; j++) {
            int kpos = kt * 32 + tx * 4 + j;
            bool ok = (amask[b * S_ + kpos] != 0);
            float sa = s0[j] * scale, sb = s1[j] * scale;
            if (win >= 0) {
                int qa_ = q0 + r0, qb_ = q0 + r1;
                if (abs(qa_ - kpos) > win) sa = -1e30f;
                if (abs(qb_ - kpos) > win) sb = -1e30f;
            }
            if (!ok) { sa = -1e30f; sb = -1e30f; }
            s0[j] = sa; s1[j] = sb;
        }
        {
            float tm = fmaxf(fmaxf(s0[0], s0[1]), fmaxf(s0[2], s0[3]));
            #pragma unroll
            for (int o = 4; o; o >>= 1) tm = fmaxf(tm, __shfl_xor_sync(0xffffffffu, tm, o));
            float nm = fmaxf(m0, tm);
            float alpha = expf(m0 - nm);
            float ps = 0.f;
            #pragma unroll
            for (int j = 0; j < 4; j++) {
                float p = expf(s0[j] - nm);
                Ps[r0][tx * 4 + j] = p;
                ps += p;
            }
            #pragma unroll
            for (int o = 4; o; o >>= 1) ps += __shfl_xor_sync(0xffffffffu, ps, o);
            l0 = l0 * alpha + ps; m0 = nm;
            #pragma unroll
            for (int j = 0; j < 8; j++) o0[j] *= alpha;
        }
        {
            float tm = fmaxf(fmaxf(s1[0], s1[1]), fmaxf(s1[2], s1[3]));
            #pragma unroll
            for (int o = 4; o; o >>= 1) tm = fmaxf(tm, __shfl_xor_sync(0xffffffffu, tm, o));
            float nm = fmaxf(m1, tm);
            float alpha = expf(m1 - nm);
            float ps = 0.f;
            #pragma unroll
            for (int j = 0; j < 4; j++) {
                float p = expf(s1[j] - nm);
                Ps[r1][tx * 4 + j] = p;
                ps += p;
            }
            #pragma unroll
            for (int o = 4; o; o >>= 1) ps += __shfl_xor_sync(0xffffffffu, ps, o);
            l1 = l1 * alpha + ps; m1 = nm;
            #pragma unroll
            for (int j = 0; j < 8; j++) o1[j] *= alpha;
        }
        __syncthreads();
        #pragma unroll 4
        for (int kk = 0; kk < 32; kk++) {
            float p0 = Ps[r0][kk], p1 = Ps[r1][kk];
            #pragma unroll
            for (int j = 0; j < 8; j++) {
                float vv = Vs[kk][d0 + j];
                o0[j] = fmaf(p0, vv, o0[j]);
                o1[j] = fmaf(p1, vv, o1[j]);
            }
        }
        __syncthreads();
    }

    float il0 = 1.0f / l0, il1 = 1.0f / l1;
    size_t base0 = (size_t)(b * S_ + q0 + r0) * (H_ * HD_) + h * HD_ + d0;
    size_t base1 = (size_t)(b * S_ + q0 + r1) * (H_ * HD_) + h * HD_ + d0;
    #pragma unroll
    for (int j = 0; j < 8; j++) {
        out[base0 + j] = o0[j] * il0;
        out[base1 + j] = o1[j] * il1;
    }
}

// ---------------- SwiGLU elementwise: gate = silu(gate) * up ----------------
__global__ void silu_mul_kernel(float* __restrict__ gate,
                                const float* __restrict__ up, int n) {
    int i = blockIdx.x * blockDim.x + threadIdx.x;
    if (i < n) {
        float g = gate[i];
        float s = g / (1.0f + expf(-g));
        gate[i] = s * up[i];
    }
}

// ---------------- host orchestration ----------------
extern "C" void kernel_launch(void* const* d_in, const int* in_sizes, int n_in,
                              void* d_out, int out_size) {
    const float* x      = (const float*)d_in[0];
    const float* wq     = (const float*)d_in[1];
    const float* wk     = (const float*)d_in[2];
    const float* wv     = (const float*)d_in[3];
    const float* wo     = (const float*)d_in[4];
    const float* qnw    = (const float*)d_in[5];
    const float* knw    = (const float*)d_in[6];
    const float* ln1    = (const float*)d_in[7];
    const float* ln2    = (const float*)d_in[8];
    const float* wg     = (const float*)d_in[9];
    const float* wu     = (const float*)d_in[10];
    const float* wd     = (const float*)d_in[11];
    const float* normw  = (const float*)d_in[12];
    const int*   amask  = (const int*)d_in[13];

    float *h, *n, *q, *k, *v, *att, *gate, *up;
    cudaGetSymbolAddress((void**)&h,    g_h);
    cudaGetSymbolAddress((void**)&n,    g_n);
    cudaGetSymbolAddress((void**)&q,    g_q);
    cudaGetSymbolAddress((void**)&k,    g_k);
    cudaGetSymbolAddress((void**)&v,    g_v);
    cudaGetSymbolAddress((void**)&att,  g_att);
    cudaGetSymbolAddress((void**)&gate, g_gate);
    cudaGetSymbolAddress((void**)&up,   g_up);

    cudaMemcpyAsync(h, x, (size_t)TOK_ * D_ * sizeof(float),
                    cudaMemcpyDeviceToDevice, 0);

    dim3 gQKV (16, TOK_ / 128);              // 512 blocks
    dim3 gGU  (48, TOK_ / 128);              // 1536 blocks
    dim3 g1024(D_ / 128, TOK_ / 128);        // 256 blocks

    for (int l = 0; l < L_; l++) {
        const float* wq_l = wq + (size_t)l * D_ * H_ * HD_;
        const float* wk_l = wk + (size_t)l * D_ * HK_ * HD_;
        const float* wv_l = wv + (size_t)l * D_ * HK_ * HD_;
        const float* wo_l = wo + (size_t)l * H_ * HD_ * D_;
        const float* wg_l = wg + (size_t)l * D_ * FF_;
        const float* wu_l = wu + (size_t)l * D_ * FF_;
        const float* wd_l = wd + (size_t)l * FF_ * D_;

        rmsnorm_kernel<<<TOK_, 256>>>(h, ln1 + l * D_, n);

        gemm_qkv<<<gQKV, 256>>>(n, wq_l, wk_l, wv_l, q, k, v);

        qknorm_rope_kernel<<<(TOK_ * H_)  / 4, 128>>>(q, qnw + l * HD_, H_);
        qknorm_rope_kernel<<<(TOK_ * HK_) / 4, 128>>>(k, knw + l * HD_, HK_);

        attn_kernel<<<dim3(S_ / 64, H_, B_), 256>>>(
            q, k, v, amask, att, (l & 1) ? WIN_ : -1);

        gemm_tf32<true><<<g1024, 256>>>(att, wo_l, h, D_, H_ * HD_);

        rmsnorm_kernel<<<TOK_, 256>>>(h, ln2 + l * D_, n);

        gemm_gateup<<<gGU, 256>>>(n, wg_l, wu_l, gate, up);

        int nel = TOK_ * FF_;
        silu_mul_kernel<<<(nel + 255) / 256, 256>>>(gate, up, nel);

        gemm_tf32<true><<<g1024, 256>>>(gate, wd_l, h, D_, FF_);
    }

    rmsnorm_kernel<<<TOK_, 256>>>(h, normw, (float*)d_out);
}